// round 9
// baseline (speedup 1.0000x reference)
#include <cuda_runtime.h>
#include <cuda_fp16.h>

#define BSZ 1024
#define T1  127
#define TP  128
#define HD  128
#define HE  128
#define ZD  512
#define GMAX 7
#define NCTA 147
#define THREADS 1024
#define ZPB 520          // zp batch stride (bank-conflict pad)
#define ZPH (7*ZPB)      // 3640

__device__ __half g_prex[(size_t)BSZ * TP * HE];   // 33.5 MB
__device__ float  g_px2[BSZ * T1];
__device__ __half g_whh[HD * ZD];                  // Wh fp16

static __device__ __forceinline__ float tanh_ap(float x){
    float r; asm("tanh.approx.f32 %0, %1;" : "=f"(r) : "f"(x)); return r;
}
static __device__ __forceinline__ float sig_ap(float x){
    return fmaf(0.5f, tanh_ap(0.5f * x), 0.5f);
}
static __device__ __forceinline__ unsigned tanh2_ap(unsigned x){
    unsigned r; asm("tanh.approx.f16x2 %0, %1;" : "=r"(r) : "r"(x)); return r;
}
static __device__ __forceinline__ unsigned h2u(__half2 h){
    union { __half2 h; unsigned u; } v; v.h = h; return v.u;
}
static __device__ __forceinline__ __half2 u2h(unsigned u){
    union { __half2 h; unsigned u; } v; v.u = u; return v.h;
}

#define FMA2(d,a,b,c)  asm("fma.rn.f32x2 %0, %1, %2, %3;" : "=l"(d) : "l"(a), "l"(b), "l"(c))
#define PACKB(d,x)     asm("mov.b64 %0, {%1,%1};" : "=l"(d) : "f"(x))
#define PACK2(d,x,y)   asm("mov.b64 %0, {%1,%2};" : "=l"(d) : "f"(x), "f"(y))
#define UNPACK2(x,y,d) asm("mov.b64 {%0,%1}, %2;" : "=f"(x), "=f"(y) : "l"(d))

#define BARS(id, n) asm volatile("bar.sync %0, %1;" :: "r"(id), "r"(n) : "memory")
#define BARA(id, n) asm volatile("bar.arrive %0, %1;" :: "r"(id), "r"(n) : "memory")

// ---------------------------------------------------------------------------
// Prepass (+ Wh -> fp16 in blocks 0..255)
// ---------------------------------------------------------------------------
#define PRE_SMEM ((HD*HE + T1*HE) * 4)

__global__ void __launch_bounds__(256, 1)
prex_kernel(const float* __restrict__ X, const float* __restrict__ W1,
            const float* __restrict__ b1, const float* __restrict__ Wfc,
            const float* __restrict__ Wh)
{
    extern __shared__ float sm[];
    float* sW = sm;
    float* sX = sm + HD * HE;
    int b = blockIdx.x;
    int tid = threadIdx.x, lane = tid & 31, wid = tid >> 5;
    const float* Xb = X + (size_t)b * T1 * HE;

    if (b < 256) g_whh[b * 256 + tid] = __float2half(Wh[b * 256 + tid]);

    for (int i = tid; i < HD * HE; i += 256) sW[i] = W1[2 * HD * HE + i];
    for (int i = tid; i < T1 * HE; i += 256) sX[i] = Xb[i];
    __syncthreads();

    int e = tid & 127, th = tid >> 7;
    float b1e = b1[e];
    for (int t = th; t < T1; t += 2) {
        float acc = 0.f;
        const float* xr = sX + t * HE;
        #pragma unroll 8
        for (int k = 0; k < HE; k++) acc = fmaf(xr[k], sW[k * HE + e], acc);
        g_prex[((size_t)b * TP + t) * HE + e] = __float2half(acc + b1e);
    }
    if (tid < 128) g_prex[((size_t)b * TP + 127) * HE + tid] = __float2half(0.f);

    float4 wf = ((const float4*)Wfc)[lane];
    for (int t = wid; t < T1; t += 8) {
        float4 x = ((const float4*)(sX + t * HE))[lane];
        float p = x.x * wf.x + x.y * wf.y + x.z * wf.z + x.w * wf.w;
        #pragma unroll
        for (int m = 16; m; m >>= 1) p += __shfl_xor_sync(0xffffffffu, p, m);
        if (lane == 0) g_px2[b * T1 + t] = p;
    }
}

// ---------------------------------------------------------------------------
// Main kernel: 147 CTAs x 7 batches x 1024 threads, warp-specialized
// ---------------------------------------------------------------------------
#define O_W1H  0
#define O_VA   16384                  // [4][7][128] = 3584
#define O_ZP   (O_VA + 3584)          // [4][7][ZPB] = 14560
#define O_D    (O_ZP + 14560)         // 1024 (transposed [k][8])
#define O_C    (O_D + 1024)           // 1024
#define O_BETA (O_C + 1024)           // 896
#define O_PX2  (O_BETA + 896)         // 896
#define O_YP   (O_PX2 + 896)          // 896
#define O_W2   (O_YP + 896)           // 128
#define O_WX   (O_W2 + 128)           // 512
#define O_BL   (O_WX + 512)           // 512
#define O_SSB  (O_BL + 512)           // 16
#define O_SQ   (O_SSB + 16)           // 8
#define MAIN_FLOATS (O_SQ + 8)
#define MAIN_SMEM (MAIN_FLOATS * 4)   // 161,760 B

struct Ctx {
    __half2* sW1h; float* sva; float* szp; float* sd; float* sc; float* sbeta;
    float* spx2; float* syp; float* sW2; float* sWx; float* sbl; float* ssb; float* sq;
};

static __device__ __forceinline__ void phaseB(const Ctx& cx, int b0, int b, int half_,
                                              int lane, bool last, float b2v)
{
    float4 vr = make_float4(0.f, 0.f, 0.f, 0.f);
    #pragma unroll
    for (int h = 0; h < 4; h++) {
        float4 a = ((const float4*)(cx.sva + h*896 + b*128))[lane];
        vr.x += a.x; vr.y += a.y; vr.z += a.z; vr.w += a.w;
    }
    float4 w2r = ((const float4*)cx.sW2)[lane];
    __half2 vr01 = __floats2half2_rn(vr.x, vr.y);
    __half2 vr23 = __floats2half2_rn(vr.z, vr.w);
    __half2 w01  = __floats2half2_rn(w2r.x, w2r.y);
    __half2 w23  = __floats2half2_rn(w2r.z, w2r.w);

    const uint2* pxb = ((const uint2*)(g_prex + (size_t)(b0 + b) * TP * HE)) + lane;
    const float* px2b = cx.spx2 + b * 128;
    float s_l = 0.f;
    int tp0 = half_ * 64;

    uint2 c0 = pxb[(tp0+0)*32], c1 = pxb[(tp0+1)*32];
    uint2 c2 = pxb[(tp0+2)*32], c3 = pxb[(tp0+3)*32];

    #pragma unroll 1
    for (int tc = 0; tc < 64; tc += 4) {
        int tp = tp0 + tc;
        int tn = (tc + 4 < 64) ? tp + 4 : tp;
        uint2 n0 = pxb[(tn+0)*32], n1 = pxb[(tn+1)*32];
        uint2 n2 = pxb[(tn+2)*32], n3 = pxb[(tn+3)*32];

        __half2 h0a = u2h(tanh2_ap(h2u(__hadd2(u2h(c0.x), vr01))));
        __half2 h0b = u2h(tanh2_ap(h2u(__hadd2(u2h(c0.y), vr23))));
        __half2 h1a = u2h(tanh2_ap(h2u(__hadd2(u2h(c1.x), vr01))));
        __half2 h1b = u2h(tanh2_ap(h2u(__hadd2(u2h(c1.y), vr23))));
        __half2 h2a = u2h(tanh2_ap(h2u(__hadd2(u2h(c2.x), vr01))));
        __half2 h2b = u2h(tanh2_ap(h2u(__hadd2(u2h(c2.y), vr23))));
        __half2 h3a = u2h(tanh2_ap(h2u(__hadd2(u2h(c3.x), vr01))));
        __half2 h3b = u2h(tanh2_ap(h2u(__hadd2(u2h(c3.y), vr23))));

        __half2 p0 = __hfma2(h0b, w23, __hmul2(h0a, w01));
        __half2 p1 = __hfma2(h1b, w23, __hmul2(h1a, w01));
        __half2 p2 = __hfma2(h2b, w23, __hmul2(h2a, w01));
        __half2 p3 = __hfma2(h3b, w23, __hmul2(h3a, w01));
        float2 q0 = __half22float2(p0);
        float2 q1 = __half22float2(p1);
        float2 q2 = __half22float2(p2);
        float2 q3 = __half22float2(p3);
        float pl0 = q0.x + q0.y, pl1 = q1.x + q1.y;
        float pl2 = q2.x + q2.y, pl3 = q3.x + q3.y;

        s_l = fmaf(pl0, px2b[tp+0], s_l);
        s_l = fmaf(pl1, px2b[tp+1], s_l);
        s_l = fmaf(pl2, px2b[tp+2], s_l);
        s_l = fmaf(pl3, px2b[tp+3], s_l);

        if (last) {
            float r0 = pl0, r1 = pl1, r2 = pl2, r3 = pl3;
            #pragma unroll
            for (int m = 16; m; m >>= 1) {
                r0 += __shfl_xor_sync(0xffffffffu, r0, m);
                r1 += __shfl_xor_sync(0xffffffffu, r1, m);
                r2 += __shfl_xor_sync(0xffffffffu, r2, m);
                r3 += __shfl_xor_sync(0xffffffffu, r3, m);
            }
            if (lane == 0) {
                cx.sbeta[b*128 + tp+0] = r0 + b2v;
                cx.sbeta[b*128 + tp+1] = r1 + b2v;
                cx.sbeta[b*128 + tp+2] = r2 + b2v;
                cx.sbeta[b*128 + tp+3] = r3 + b2v;
            }
        }
        c0 = n0; c1 = n1; c2 = n2; c3 = n3;
    }
    #pragma unroll
    for (int m = 16; m; m >>= 1) s_l += __shfl_xor_sync(0xffffffffu, s_l, m);
    if (lane == 0) cx.ssb[2*b + half_] = s_l;
}

// Phase C: zp = d @ Wh, group2 (512 threads), transposed state, f32x2
static __device__ __forceinline__ void phaseC(const Ctx& cx, int tid2)
{
    int jg = tid2 & 127, h = tid2 >> 7, kb = h * 32;
    const __half* whp = g_whh + (size_t)kb * ZD + jg * 4;
    unsigned long long a01[GMAX], a23[GMAX];
    #pragma unroll
    for (int b = 0; b < GMAX; b++) { a01[b] = 0ULL; a23[b] = 0ULL; }

    uint2 wc0 = *(const uint2*)(whp + 0*ZD);
    uint2 wc1 = *(const uint2*)(whp + 1*ZD);
    uint2 wc2 = *(const uint2*)(whp + 2*ZD);
    uint2 wc3 = *(const uint2*)(whp + 3*ZD);

#define CROW(WREG, KROW) do { \
    float2 lo_ = __half22float2(u2h((WREG).x)); \
    float2 hi_ = __half22float2(u2h((WREG).y)); \
    unsigned long long w01_, w23_; \
    PACK2(w01_, lo_.x, lo_.y); PACK2(w23_, hi_.x, hi_.y); \
    float4 dA_ = *(const float4*)(cx.sd + (KROW)*8); \
    float4 dB_ = *(const float4*)(cx.sd + (KROW)*8 + 4); \
    unsigned long long dd_; \
    PACKB(dd_, dA_.x); FMA2(a01[0], dd_, w01_, a01[0]); FMA2(a23[0], dd_, w23_, a23[0]); \
    PACKB(dd_, dA_.y); FMA2(a01[1], dd_, w01_, a01[1]); FMA2(a23[1], dd_, w23_, a23[1]); \
    PACKB(dd_, dA_.z); FMA2(a01[2], dd_, w01_, a01[2]); FMA2(a23[2], dd_, w23_, a23[2]); \
    PACKB(dd_, dA_.w); FMA2(a01[3], dd_, w01_, a01[3]); FMA2(a23[3], dd_, w23_, a23[3]); \
    PACKB(dd_, dB_.x); FMA2(a01[4], dd_, w01_, a01[4]); FMA2(a23[4], dd_, w23_, a23[4]); \
    PACKB(dd_, dB_.y); FMA2(a01[5], dd_, w01_, a01[5]); FMA2(a23[5], dd_, w23_, a23[5]); \
    PACKB(dd_, dB_.z); FMA2(a01[6], dd_, w01_, a01[6]); FMA2(a23[6], dd_, w23_, a23[6]); \
} while(0)

    #pragma unroll 1
    for (int kk = 0; kk < 32; kk += 4) {
        int kn = (kk + 4 < 32) ? kk + 4 : kk;
        uint2 n0 = *(const uint2*)(whp + (size_t)(kn+0)*ZD);
        uint2 n1 = *(const uint2*)(whp + (size_t)(kn+1)*ZD);
        uint2 n2 = *(const uint2*)(whp + (size_t)(kn+2)*ZD);
        uint2 n3 = *(const uint2*)(whp + (size_t)(kn+3)*ZD);
        CROW(wc0, kb+kk+0);
        CROW(wc1, kb+kk+1);
        CROW(wc2, kb+kk+2);
        CROW(wc3, kb+kk+3);
        wc0 = n0; wc1 = n1; wc2 = n2; wc3 = n3;
    }
#undef CROW
    #pragma unroll
    for (int b = 0; b < GMAX; b++) {
        float* p = cx.szp + h*ZPH + b*ZPB + jg*4;
        *(unsigned long long*)p       = a01[b];
        *(unsigned long long*)(p + 2) = a23[b];
    }
}

__global__ void __launch_bounds__(THREADS, 1)
decoder_kernel(const float* __restrict__ X, const float* __restrict__ yprev,
               const float* __restrict__ W1, const float* __restrict__ W2,
               const float* __restrict__ b2, const float* __restrict__ Wfc,
               const float* __restrict__ bfc, const float* __restrict__ Wx,
               const float* __restrict__ Wh, const float* __restrict__ bl,
               const float* __restrict__ Wf, const float* __restrict__ bf,
               float* __restrict__ out)
{
    extern __shared__ float sm[];
    Ctx cx;
    cx.sW1h = (__half2*)(sm + O_W1H);
    cx.sva = sm + O_VA;  cx.szp = sm + O_ZP;
    cx.sd = sm + O_D;    cx.sc = sm + O_C;    cx.sbeta = sm + O_BETA;
    cx.spx2 = sm + O_PX2; cx.syp = sm + O_YP; cx.sW2 = sm + O_W2;
    cx.sWx = sm + O_WX;  cx.sbl = sm + O_BL;  cx.ssb = sm + O_SSB; cx.sq = sm + O_SQ;

    int tid = threadIdx.x, lane = tid & 31, wid = tid >> 5;
    int b0 = blockIdx.x * GMAX;
    if (b0 >= BSZ) return;
    int nb = min(GMAX, BSZ - b0);

    for (int i = tid; i < HD * HE; i += THREADS)
        cx.sW1h[i] = __floats2half2_rn(W1[i], W1[HD * HE + i]);
    if (tid < 128) cx.sW2[tid] = W2[tid];
    if (tid < 512) { cx.sWx[tid] = Wx[tid]; cx.sbl[tid] = bl[tid]; }
    if (tid < 16) cx.ssb[tid] = 0.f;
    if (tid >= 16 && tid < 24) cx.sq[tid - 16] = 0.f;
    if (tid < GMAX * 128) {
        int b = tid >> 7, tp = tid & 127;
        bool ok = (b < nb) && (tp < T1);
        cx.spx2[tid] = ok ? g_px2[(b0 + b) * T1 + tp] : 0.f;
        cx.syp[tid]  = ok ? yprev[(size_t)(b0 + b) * T1 + tp] : 0.f;
    }
    {   // transposed state init: sd[k*8+b]
        int b = tid & 7;
        float x00 = (b < nb) ? X[(size_t)(b0 + b) * T1 * HE] : 0.f;
        cx.sd[tid] = x00; cx.sc[tid] = x00;
    }
    float b2v  = b2[0];
    float bfcv = bfc[0];
    float wfcy = Wfc[HE];
    __syncthreads();
    if (wid < nb) {
        const float* p = cx.spx2 + wid * 128;
        float v = p[lane] + p[lane+32] + p[lane+64] + p[lane+96];
        #pragma unroll
        for (int m = 16; m; m >>= 1) v += __shfl_xor_sync(0xffffffffu, v, m);
        if (lane == 0) cx.sq[wid] = v;
    }
    __syncthreads();

    if (wid < 16) {
        // ========== GROUP 1: A then B ==========
        int e = tid & 127, h = tid >> 7, kb = h * 32;
        for (int t = 0; t < T1; t++) {
            if (t > 0) BARS(2, 1024);
            // ---- Phase A: f32x2 over batch pairs ----
            {
                unsigned long long acc0 = 0, acc1 = 0, acc2 = 0, acc3 = 0;
                const __half2* wrow = cx.sW1h + e;
                #pragma unroll 4
                for (int kk = 0; kk < 32; kk++) {
                    int k = kb + kk;
                    float2 w = __half22float2(wrow[k * 128]);
                    unsigned long long wd, wc_;
                    PACKB(wd, w.x); PACKB(wc_, w.y);
                    ulonglong2 dA = *(const ulonglong2*)(cx.sd + k*8);
                    ulonglong2 dB = *(const ulonglong2*)(cx.sd + k*8 + 4);
                    ulonglong2 cA = *(const ulonglong2*)(cx.sc + k*8);
                    ulonglong2 cB = *(const ulonglong2*)(cx.sc + k*8 + 4);
                    FMA2(acc0, dA.x, wd, acc0); FMA2(acc0, cA.x, wc_, acc0);
                    FMA2(acc1, dA.y, wd, acc1); FMA2(acc1, cA.y, wc_, acc1);
                    FMA2(acc2, dB.x, wd, acc2); FMA2(acc2, cB.x, wc_, acc2);
                    FMA2(acc3, dB.y, wd, acc3); FMA2(acc3, cB.y, wc_, acc3);
                }
                float* va = cx.sva + h * 896 + e;
                float v0, v1;
                UNPACK2(v0, v1, acc0); va[0]     = v0; va[128]   = v1;
                UNPACK2(v0, v1, acc1); va[256]   = v0; va[384]   = v1;
                UNPACK2(v0, v1, acc2); va[512]   = v0; va[640]   = v1;
                UNPACK2(v0, v1, acc3); va[768]   = v0;            // b=7 pad dropped
            }
            BARS(3, 512);
            if (wid < 14) {
                int b = wid >> 1;
                if (b < nb) phaseB(cx, b0, b, wid & 1, lane, t == T1 - 1, b2v);
            }
            __threadfence_block();
            BARA(1, 1024);
        }
    } else {
        // ========== GROUP 2: C then D ==========
        int tid2 = tid - 512;
        for (int t = 0; t < T1; t++) {
            phaseC(cx, tid2);
            BARS(1, 1024);
            // ---- Phase D: gates, transposed state update ----
            #pragma unroll
            for (int rep = 0; rep < 2; rep++) {
                int i = tid2 + rep * 512;
                int b = i & 7, k = i >> 3;
                float dn = 0.f, cn = 0.f;
                if (b < GMAX) {
                    float s  = cx.ssb[2*b] + cx.ssb[2*b+1] + b2v * cx.sq[b];
                    float yt = fmaf(cx.syp[b*128 + t], wfcy, s + bfcv);
                    const float* zb = cx.szp + b * ZPB;
                    float zi = zb[k]       + zb[ZPH + k]       + zb[2*ZPH + k]       + zb[3*ZPH + k];
                    float zf = zb[128 + k] + zb[ZPH + 128 + k] + zb[2*ZPH + 128 + k] + zb[3*ZPH + 128 + k];
                    float zg = zb[256 + k] + zb[ZPH + 256 + k] + zb[2*ZPH + 256 + k] + zb[3*ZPH + 256 + k];
                    float zo = zb[384 + k] + zb[ZPH + 384 + k] + zb[2*ZPH + 384 + k] + zb[3*ZPH + 384 + k];
                    zi = fmaf(yt, cx.sWx[k],       zi + cx.sbl[k]);
                    zf = fmaf(yt, cx.sWx[128 + k], zf + cx.sbl[128 + k]);
                    zg = fmaf(yt, cx.sWx[256 + k], zg + cx.sbl[256 + k]);
                    zo = fmaf(yt, cx.sWx[384 + k], zo + cx.sbl[384 + k]);
                    float cold = cx.sc[k*8 + b];
                    cn = fmaf(sig_ap(zf), cold, sig_ap(zi) * tanh_ap(zg));
                    dn = sig_ap(zo) * tanh_ap(cn);
                }
                cx.sc[k*8 + b] = cn;
                cx.sd[k*8 + b] = dn;
            }
            __threadfence_block();
            if (t < T1 - 1) BARA(2, 1024);
            BARS(5, 512);
        }
    }
    __syncthreads();

    // ---- Epilogue: ctx from final beta; out ----
    if (wid < nb) {
        int b = wid;
        const float4* Xb = (const float4*)(X + (size_t)(b0 + b) * T1 * HE);
        float cxx = 0.f, cy = 0.f, cz = 0.f, cw = 0.f;
        for (int tp = 0; tp < T1; tp++) {
            float bb = cx.sbeta[b*128 + tp];
            float4 xv = Xb[tp*32 + lane];
            cxx = fmaf(bb, xv.x, cxx); cy = fmaf(bb, xv.y, cy);
            cz  = fmaf(bb, xv.z, cz);  cw = fmaf(bb, xv.w, cw);
        }
        float4 wfc2 = ((const float4*)(Wf + 128))[lane];
        float4 wfd  = ((const float4*)Wf)[lane];
        int e0 = lane * 4;
        float d0 = cx.sd[(e0+0)*8 + b], d1 = cx.sd[(e0+1)*8 + b];
        float d2 = cx.sd[(e0+2)*8 + b], d3 = cx.sd[(e0+3)*8 + b];
        float r = cxx*wfc2.x + cy*wfc2.y + cz*wfc2.z + cw*wfc2.w;
        r = fmaf(d0, wfd.x, r); r = fmaf(d1, wfd.y, r);
        r = fmaf(d2, wfd.z, r); r = fmaf(d3, wfd.w, r);
        #pragma unroll
        for (int m = 16; m; m >>= 1) r += __shfl_xor_sync(0xffffffffu, r, m);
        if (lane == 0) out[b0 + b] = r + bf[0];
    }
}

extern "C" void kernel_launch(void* const* d_in, const int* in_sizes, int n_in,
                              void* d_out, int out_size)
{
    const float* X    = (const float*)d_in[0];
    const float* yprev= (const float*)d_in[1];
    const float* W1   = (const float*)d_in[2];
    const float* b1   = (const float*)d_in[3];
    const float* W2   = (const float*)d_in[4];
    const float* b2   = (const float*)d_in[5];
    const float* Wfc  = (const float*)d_in[6];
    const float* bfc  = (const float*)d_in[7];
    const float* Wx   = (const float*)d_in[8];
    const float* Wh   = (const float*)d_in[9];
    const float* bl   = (const float*)d_in[10];
    const float* Wf   = (const float*)d_in[11];
    const float* bf   = (const float*)d_in[12];
    float* out = (float*)d_out;

    cudaFuncSetAttribute(prex_kernel, cudaFuncAttributeMaxDynamicSharedMemorySize, PRE_SMEM);
    cudaFuncSetAttribute(decoder_kernel, cudaFuncAttributeMaxDynamicSharedMemorySize, MAIN_SMEM);

    prex_kernel<<<BSZ, 256, PRE_SMEM>>>(X, W1, b1, Wfc, Wh);
    decoder_kernel<<<NCTA, THREADS, MAIN_SMEM>>>(X, yprev, W1, W2, b2, Wfc, bfc,
                                                 Wx, Wh, bl, Wf, bf, out);
}